// round 10
// baseline (speedup 1.0000x reference)
#include <cuda_runtime.h>
#include <cuda_bf16.h>
#include <cstdint>
#include <cstring>

// ============================================================================
// Problem constants / tiling (legacy mma.sync path — tcgen05 not available
// under the harness's compute_103 virtual arch)
// ============================================================================
namespace {
constexpr int B = 16, C = 16, P = 512, D = 256;
constexpr int BM = 128, BN = 128, BKF = 32;      // CTA tile, fp32-K per stage
constexpr int SK = 72;                            // smem row stride in halves
constexpr int TILE_HALVES = 128 * SK;             // one operand tile (hi+lo)
constexpr int STAGE_BYTES = 2 * TILE_HALVES * 2;  // A+B tile = 36864 B
constexpr int NSTAGE = 3;                         // triple buffer
constexpr int DYN_BYTES = NSTAGE * STAGE_BYTES + 1024;  // + row-stats slot
}

// ============================================================================
// Device-global scratch (no allocations allowed)
// ============================================================================
__device__ __nv_bfloat16 g_qh[(size_t)B * C * P * D];
__device__ __nv_bfloat16 g_ql[(size_t)B * C * P * D];
__device__ __nv_bfloat16 g_ch[(size_t)B * C * P * D];
__device__ __nv_bfloat16 g_cl[(size_t)B * C * P * D];
__device__ __nv_bfloat16 g_wth[(size_t)3 * C * D * D];   // W^T hi  [e][d]
__device__ __nv_bfloat16 g_wtl[(size_t)3 * C * D * D];   // W^T lo
__device__ __nv_bfloat16 g_Qh[(size_t)B * C * P * D];
__device__ __nv_bfloat16 g_Ql[(size_t)B * C * P * D];
__device__ __nv_bfloat16 g_Kh[(size_t)B * C * P * D];
__device__ __nv_bfloat16 g_Kl[(size_t)B * C * P * D];
__device__ __nv_bfloat16 g_VTh[(size_t)B * C * D * P];   // V^T [e][p]
__device__ __nv_bfloat16 g_VTl[(size_t)B * C * D * P];
__device__ float g_At[(size_t)B * C * P * P];            // scores fp32
__device__ float g_rm[(size_t)B * C * P];                // row max
__device__ float g_ri[(size_t)B * C * P];                // row 1/sum

// ============================================================================
// Helpers
// ============================================================================
__device__ __forceinline__ uint32_t smem_u32(const void* p) {
    return (uint32_t)__cvta_generic_to_shared(p);
}
__device__ __forceinline__ void ldsm_x4(uint32_t& r0, uint32_t& r1, uint32_t& r2,
                                        uint32_t& r3, uint32_t a) {
    asm volatile("ldmatrix.sync.aligned.m8n8.x4.shared.b16 {%0,%1,%2,%3}, [%4];"
                 : "=r"(r0), "=r"(r1), "=r"(r2), "=r"(r3) : "r"(a));
}
__device__ __forceinline__ void mma_bf16(float* c, const uint32_t* a, const uint32_t* b) {
    asm volatile(
        "mma.sync.aligned.m16n8k16.row.col.f32.bf16.bf16.f32 "
        "{%0,%1,%2,%3}, {%4,%5,%6,%7}, {%8,%9}, {%0,%1,%2,%3};"
        : "+f"(c[0]), "+f"(c[1]), "+f"(c[2]), "+f"(c[3])
        : "r"(a[0]), "r"(a[1]), "r"(a[2]), "r"(a[3]), "r"(b[0]), "r"(b[1]));
}
__device__ __forceinline__ void cp16(uint32_t dst, const void* src) {
    asm volatile("cp.async.cg.shared.global [%0], [%1], 16;" :: "r"(dst), "l"(src));
}
#define CP_COMMIT() asm volatile("cp.async.commit_group;" ::: "memory")
#define CP_WAIT_1() asm volatile("cp.async.wait_group 1;" ::: "memory")
#define CP_WAIT_0() asm volatile("cp.async.wait_group 0;" ::: "memory")

__device__ __forceinline__ void split1(float x, __nv_bfloat16& h, __nv_bfloat16& l) {
    h = __float2bfloat16(x);
    l = __float2bfloat16(x - __bfloat162float(h));
}
__device__ __forceinline__ uint32_t pack2(__nv_bfloat16 a, __nv_bfloat16 b) {
    __nv_bfloat162 v = __halves2bfloat162(a, b);
    uint32_t u; memcpy(&u, &v, 4); return u;
}
__device__ __forceinline__ void split_store2(__nv_bfloat16* H, __nv_bfloat16* L,
                                             size_t off, float x, float y) {
    __nv_bfloat16 hx, lx, hy, ly;
    split1(x, hx, lx); split1(y, hy, ly);
    *reinterpret_cast<__nv_bfloat162*>(H + off) = __halves2bfloat162(hx, hy);
    *reinterpret_cast<__nv_bfloat162*>(L + off) = __halves2bfloat162(lx, ly);
}

// ============================================================================
// Async stage fill: A[128x32] + B[128x32] hi/lo (K-major) -> padded smem
// ============================================================================
__device__ __forceinline__ void fill_stage(char* buf,
    const __nv_bfloat16* __restrict__ Ah, const __nv_bfloat16* __restrict__ Al,
    int lda, int m0,
    const __nv_bfloat16* __restrict__ Bh, const __nv_bfloat16* __restrict__ Bl,
    int ldb, int n0, int k0, int t)
{
    uint32_t ab = smem_u32(buf);
    uint32_t bb = ab + TILE_HALVES * 2;
#pragma unroll
    for (int i = t; i < 512; i += 128) {
        int r = i >> 2, ch = (i & 3) * 8;
        size_t sa = (size_t)(m0 + r) * lda + k0 + ch;
        cp16(ab + (r * SK + ch) * 2,      Ah + sa);
        cp16(ab + (r * SK + 32 + ch) * 2, Al + sa);
        size_t sb = (size_t)(n0 + r) * ldb + k0 + ch;
        cp16(bb + (r * SK + ch) * 2,      Bh + sb);
        cp16(bb + (r * SK + 32 + ch) * 2, Bl + sb);
    }
    CP_COMMIT();
}

// B-only async fill (for k_av, where A comes from fp32 scores + exp)
__device__ __forceinline__ void fill_B(char* buf,
    const __nv_bfloat16* __restrict__ Bh, const __nv_bfloat16* __restrict__ Bl,
    int ldb, int n0, int k0, int t)
{
    uint32_t bb = smem_u32(buf) + TILE_HALVES * 2;
#pragma unroll
    for (int i = t; i < 512; i += 128) {
        int r = i >> 2, ch = (i & 3) * 8;
        size_t sb = (size_t)(n0 + r) * ldb + k0 + ch;
        cp16(bb + (r * SK + ch) * 2,      Bh + sb);
        cp16(bb + (r * SK + 32 + ch) * 2, Bl + sb);
    }
    CP_COMMIT();
}

// A fill with fused softmax: load fp32 scores, apply exp(x-m)*inv, split hi/lo.
// NOTE: reads s_m/s_inv written by OTHER threads — callers must ensure a
// __syncthreads() separates the s_m/s_inv stores from any call to this.
__device__ __forceinline__ void fill_A_exp(char* buf,
    const float* __restrict__ At /* pre-offset to (bc,m0) */, int k0, int t,
    const float* __restrict__ s_m, const float* __restrict__ s_inv)
{
#pragma unroll
    for (int j = 0; j < 8; ++j) {
        int i = j * 128 + t;
        int row = i >> 3, c4 = (i & 7) * 4;
        float4 v = *reinterpret_cast<const float4*>(At + (size_t)row * P + k0 + c4);
        float m = s_m[row], inv = s_inv[row];
        float e0 = __expf(v.x - m) * inv, e1 = __expf(v.y - m) * inv;
        float e2 = __expf(v.z - m) * inv, e3 = __expf(v.w - m) * inv;
        __nv_bfloat16 h0, l0, h1, l1, h2, l2, h3, l3;
        split1(e0, h0, l0); split1(e1, h1, l1);
        split1(e2, h2, l2); split1(e3, h3, l3);
        __nv_bfloat16* base = reinterpret_cast<__nv_bfloat16*>(buf);
        *reinterpret_cast<uint2*>(base + row * SK + c4) =
            make_uint2(pack2(h0, h1), pack2(h2, h3));
        *reinterpret_cast<uint2*>(base + row * SK + 32 + c4) =
            make_uint2(pack2(l0, l1), pack2(l2, l3));
    }
}

// ============================================================================
// One-stage compute: 64x64 warp tile, 2 k16 steps, 3-MMA hi/lo split
// ============================================================================
__device__ __forceinline__ void compute_stage(const __nv_bfloat16* As,
                                              const __nv_bfloat16* Bs,
                                              float acc[4][8][4], int lane, int wid)
{
    int wm = (wid & 1) * 64;
    int wn = (wid >> 1) * 64;
    int lr = lane & 7, lm = lane >> 3;
    int a_row = (lm & 1) * 8 + lr;
    int a_col = (lm >> 1) * 8;
    int b_row = (lm >> 1) * 8 + lr;
    int b_col = (lm & 1) * 8;
#pragma unroll
    for (int ks = 0; ks < 2; ++ks) {
        int k0 = ks * 16;
        uint32_t Ahf[4][4], Alf[4][4];
#pragma unroll
        for (int mt = 0; mt < 4; ++mt) {
            uint32_t a = smem_u32(&As[(wm + mt * 16 + a_row) * SK + k0 + a_col]);
            ldsm_x4(Ahf[mt][0], Ahf[mt][1], Ahf[mt][2], Ahf[mt][3], a);
            uint32_t al = smem_u32(&As[(wm + mt * 16 + a_row) * SK + 32 + k0 + a_col]);
            ldsm_x4(Alf[mt][0], Alf[mt][1], Alf[mt][2], Alf[mt][3], al);
        }
#pragma unroll
        for (int h = 0; h < 2; ++h) {
            uint32_t Bhf[4][2], Blf[4][2];
#pragma unroll
            for (int jp = 0; jp < 2; ++jp) {
                uint32_t b = smem_u32(&Bs[(wn + h * 32 + jp * 16 + b_row) * SK + k0 + b_col]);
                ldsm_x4(Bhf[2 * jp][0], Bhf[2 * jp][1], Bhf[2 * jp + 1][0], Bhf[2 * jp + 1][1], b);
                uint32_t bl = smem_u32(&Bs[(wn + h * 32 + jp * 16 + b_row) * SK + 32 + k0 + b_col]);
                ldsm_x4(Blf[2 * jp][0], Blf[2 * jp][1], Blf[2 * jp + 1][0], Blf[2 * jp + 1][1], bl);
            }
#pragma unroll
            for (int mt = 0; mt < 4; ++mt)
#pragma unroll
                for (int j = 0; j < 4; ++j) {
                    int nt = h * 4 + j;
                    mma_bf16(acc[mt][nt], Ahf[mt], Bhf[j]);
                    mma_bf16(acc[mt][nt], Ahf[mt], Blf[j]);
                    mma_bf16(acc[mt][nt], Alf[mt], Bhf[j]);
                }
        }
    }
}

// ============================================================================
// 3-stage pipelined K loop, ONE __syncthreads per stage.
// fill(s+2) after sync_s targets buffer (s-1)%3 whose compute finished at s-1
// (guaranteed by sync_s) — no trailing barrier needed.
// ============================================================================
__device__ __forceinline__ void gemm_tiles3(char* dyn,
    const __nv_bfloat16* Ah, const __nv_bfloat16* Al, int lda, int m0,
    const __nv_bfloat16* Bh, const __nv_bfloat16* Bl, int ldb, int n0,
    int S, float acc[4][8][4], int t, int lane, int wid)
{
    fill_stage(dyn,               Ah, Al, lda, m0, Bh, Bl, ldb, n0, 0,   t);
    fill_stage(dyn + STAGE_BYTES, Ah, Al, lda, m0, Bh, Bl, ldb, n0, BKF, t);
    for (int s = 0; s < S; ++s) {
        if (s == S - 1) { CP_WAIT_0(); } else { CP_WAIT_1(); }
        __syncthreads();
        if (s + 2 < S)
            fill_stage(dyn + ((s + 2) % NSTAGE) * STAGE_BYTES, Ah, Al, lda, m0,
                       Bh, Bl, ldb, n0, (s + 2) * BKF, t);
        char* buf = dyn + (s % NSTAGE) * STAGE_BYTES;
        compute_stage(reinterpret_cast<const __nv_bfloat16*>(buf),
                      reinterpret_cast<const __nv_bfloat16*>(buf + TILE_HALVES * 2),
                      acc, lane, wid);
    }
}

// Variant for AV: A tiles built from fp32 scores with fused exp; B via cp.async.
// Caller must __syncthreads() between writing s_m/s_inv and calling this.
__device__ __forceinline__ void gemm_tiles3_av(char* dyn,
    const float* At, const __nv_bfloat16* Bh, const __nv_bfloat16* Bl,
    int ldb, int n0, int S, float acc[4][8][4], int t, int lane, int wid,
    const float* s_m, const float* s_inv)
{
    fill_B(dyn,               Bh, Bl, ldb, n0, 0,   t);
    fill_A_exp(dyn,               At, 0,   t, s_m, s_inv);
    fill_B(dyn + STAGE_BYTES, Bh, Bl, ldb, n0, BKF, t);
    fill_A_exp(dyn + STAGE_BYTES, At, BKF, t, s_m, s_inv);
    for (int s = 0; s < S; ++s) {
        if (s == S - 1) { CP_WAIT_0(); } else { CP_WAIT_1(); }
        __syncthreads();
        if (s + 2 < S) {
            char* nb = dyn + ((s + 2) % NSTAGE) * STAGE_BYTES;
            fill_B(nb, Bh, Bl, ldb, n0, (s + 2) * BKF, t);
            fill_A_exp(nb, At, (s + 2) * BKF, t, s_m, s_inv);
        }
        char* buf = dyn + (s % NSTAGE) * STAGE_BYTES;
        compute_stage(reinterpret_cast<const __nv_bfloat16*>(buf),
                      reinterpret_cast<const __nv_bfloat16*>(buf + TILE_HALVES * 2),
                      acc, lane, wid);
    }
}

// ============================================================================
// Kernel 1: fused S + split of query / context into bf16 hi/lo
// ============================================================================
__global__ void k_prep(const float* __restrict__ query, const float* __restrict__ aw)
{
    const int PD4 = P * D / 4;
    int i = blockIdx.x * blockDim.x + threadIdx.x;   // over B*P*D/4
    int b = i / PD4;
    int pd4 = i - b * PD4;
    const float4* q4 = reinterpret_cast<const float4*>(query);
    const float4* a4 = reinterpret_cast<const float4*>(aw);
    float4 q[C];
    float4 S = make_float4(0.f, 0.f, 0.f, 0.f);
#pragma unroll
    for (int c = 0; c < C; ++c) {
        q[c] = q4[((size_t)b * C + c) * PD4 + pd4];
        float4 a = a4[c * PD4 + pd4];
        S.x += a.x * q[c].x; S.y += a.y * q[c].y;
        S.z += a.z * q[c].z; S.w += a.w * q[c].w;
    }
#pragma unroll
    for (int c = 0; c < C; ++c) {
        float4 a = a4[c * PD4 + pd4];
        float cx = S.x - a.x * q[c].x, cy = S.y - a.y * q[c].y;
        float cz = S.z - a.z * q[c].z, cw = S.w - a.w * q[c].w;
        size_t off = (((size_t)b * C + c) * PD4 + pd4) * 4;
        split_store2(g_qh, g_ql, off,     q[c].x, q[c].y);
        split_store2(g_qh, g_ql, off + 2, q[c].z, q[c].w);
        split_store2(g_ch, g_cl, off,     cx, cy);
        split_store2(g_ch, g_cl, off + 2, cz, cw);
    }
}

// ============================================================================
// Kernel 2: weights -> transposed bf16 hi/lo  (W[d][e] -> Wt[e][d])
// ============================================================================
__global__ void k_prep_wt(const float* __restrict__ Wq, const float* __restrict__ Wk,
                          const float* __restrict__ Wv)
{
    const int CDD4 = C * D * D / 4;
    int i = blockIdx.x * blockDim.x + threadIdx.x;
    int which = i / CDD4;
    int j = i - which * CDD4;
    int c = j / (D * D / 4);
    int j2 = j - c * (D * D / 4);
    int k = j2 / (D / 4);
    int n4 = (j2 - k * (D / 4)) * 4;
    const float* W = (which == 0) ? Wq : (which == 1) ? Wk : Wv;
    float4 v = *reinterpret_cast<const float4*>(W + ((size_t)c * D + k) * D + n4);
    float vv[4] = {v.x, v.y, v.z, v.w};
    size_t base = ((size_t)which * C + c) * D * D;
#pragma unroll
    for (int e = 0; e < 4; ++e) {
        __nv_bfloat16 h, l;
        split1(vv[e], h, l);
        g_wth[base + (size_t)(n4 + e) * D + k] = h;
        g_wtl[base + (size_t)(n4 + e) * D + k] = l;
    }
}

// ============================================================================
// Kernel 3: Q/K projections. grid(x=2, y=4, z=bc*2+which), 128 thr
// ============================================================================
__global__ void __launch_bounds__(128) k_projQK(const float* __restrict__ bq,
                                                const float* __restrict__ bk)
{
    extern __shared__ char dyn[];
    int z = blockIdx.z;
    int which = z & 1;
    int bc = z >> 1;
    int c = bc & 15;
    int m0 = blockIdx.y * BM, n0 = blockIdx.x * BN;
    int t = threadIdx.x, lane = t & 31, wid = t >> 5;

    size_t abase = (size_t)bc * P * D;
    const __nv_bfloat16* Ah = (which == 0 ? g_qh : g_ch) + abase;
    const __nv_bfloat16* Al = (which == 0 ? g_ql : g_cl) + abase;
    size_t wbase = ((size_t)which * C + c) * D * D;

    float acc[4][8][4] = {};
    gemm_tiles3(dyn, Ah, Al, D, m0, g_wth + wbase, g_wtl + wbase, D, n0,
                D / BKF, acc, t, lane, wid);

    const float* bias = which ? bk : bq;
    float scale = which ? 1.0f : 0.0625f;
    __nv_bfloat16* OH = which ? g_Kh : g_Qh;
    __nv_bfloat16* OL = which ? g_Kl : g_Ql;
    int wm = (wid & 1) * 64, wn = (wid >> 1) * 64;
    int gr = lane >> 2, gc = (lane & 3) * 2;
#pragma unroll
    for (int mt = 0; mt < 4; ++mt)
#pragma unroll
        for (int nt = 0; nt < 8; ++nt) {
            int p0 = m0 + wm + mt * 16 + gr;
            int e0 = n0 + wn + nt * 8 + gc;
            float2 bb = *reinterpret_cast<const float2*>(&bias[c * D + e0]);
            float v0 = fmaxf(acc[mt][nt][0] + bb.x, 0.f) * scale;
            float v1 = fmaxf(acc[mt][nt][1] + bb.y, 0.f) * scale;
            float v2 = fmaxf(acc[mt][nt][2] + bb.x, 0.f) * scale;
            float v3 = fmaxf(acc[mt][nt][3] + bb.y, 0.f) * scale;
            split_store2(OH, OL, abase + (size_t)p0 * D + e0, v0, v1);
            split_store2(OH, OL, abase + (size_t)(p0 + 8) * D + e0, v2, v3);
        }
}

// ============================================================================
// Kernel 4: V^T projection. Vt[e][p] = relu(Wt[e][:]·ctx[p][:] + bv[e])
// grid(x=4 over p, y=2 over e, z=bc), 128 thr
// ============================================================================
__global__ void __launch_bounds__(128) k_projVT(const float* __restrict__ bv)
{
    extern __shared__ char dyn[];
    int bc = blockIdx.z;
    int c = bc & 15;
    int m0 = blockIdx.y * BM;          // e
    int n0 = blockIdx.x * BN;          // p
    int t = threadIdx.x, lane = t & 31, wid = t >> 5;

    size_t cbase = (size_t)bc * P * D;
    size_t wbase = ((size_t)2 * C + c) * D * D;
    float acc[4][8][4] = {};
    gemm_tiles3(dyn, g_wth + wbase, g_wtl + wbase, D, m0,
                g_ch + cbase, g_cl + cbase, D, n0, D / BKF, acc, t, lane, wid);

    int wm = (wid & 1) * 64, wn = (wid >> 1) * 64;
    int gr = lane >> 2, gc = (lane & 3) * 2;
    size_t obase = (size_t)bc * D * P;
#pragma unroll
    for (int mt = 0; mt < 4; ++mt)
#pragma unroll
        for (int nt = 0; nt < 8; ++nt) {
            int e0 = m0 + wm + mt * 16 + gr;
            int p0 = n0 + wn + nt * 8 + gc;
            float b0 = bv[c * D + e0], b1 = bv[c * D + e0 + 8];
            float v0 = fmaxf(acc[mt][nt][0] + b0, 0.f);
            float v1 = fmaxf(acc[mt][nt][1] + b0, 0.f);
            float v2 = fmaxf(acc[mt][nt][2] + b1, 0.f);
            float v3 = fmaxf(acc[mt][nt][3] + b1, 0.f);
            split_store2(g_VTh, g_VTl, obase + (size_t)e0 * P + p0, v0, v1);
            split_store2(g_VTh, g_VTl, obase + (size_t)(e0 + 8) * P + p0, v2, v3);
        }
}

// ============================================================================
// Kernel 5: scores = Q @ K^T. grid(x=4, y=4, z=bc), 128 thr
// ============================================================================
__global__ void __launch_bounds__(128) k_scores_m()
{
    extern __shared__ char dyn[];
    int bc = blockIdx.z;
    int m0 = blockIdx.y * BM, n0 = blockIdx.x * BN;
    int t = threadIdx.x, lane = t & 31, wid = t >> 5;
    size_t base = (size_t)bc * P * D;

    float acc[4][8][4] = {};
    gemm_tiles3(dyn, g_Qh + base, g_Ql + base, D, m0,
                g_Kh + base, g_Kl + base, D, n0, D / BKF, acc, t, lane, wid);

    int wm = (wid & 1) * 64, wn = (wid >> 1) * 64;
    int gr = lane >> 2, gc = (lane & 3) * 2;
    float* Out = g_At + (size_t)bc * P * P;
#pragma unroll
    for (int mt = 0; mt < 4; ++mt)
#pragma unroll
        for (int nt = 0; nt < 8; ++nt) {
            int p0 = m0 + wm + mt * 16 + gr;
            int q0 = n0 + wn + nt * 8 + gc;
            *reinterpret_cast<float2*>(&Out[(size_t)p0 * P + q0]) =
                make_float2(acc[mt][nt][0], acc[mt][nt][1]);
            *reinterpret_cast<float2*>(&Out[(size_t)(p0 + 8) * P + q0]) =
                make_float2(acc[mt][nt][2], acc[mt][nt][3]);
        }
}

// ============================================================================
// Kernel 6: row stats (max, 1/sum of exp) — softmax itself is fused into AV
// ============================================================================
__global__ void k_stats()
{
    size_t row = blockIdx.x;
    int t = threadIdx.x;
    const float4* r = reinterpret_cast<const float4*>(g_At + row * P);
    float4 v = r[t];
    float m = fmaxf(fmaxf(v.x, v.y), fmaxf(v.z, v.w));
#pragma unroll
    for (int o = 16; o > 0; o >>= 1) m = fmaxf(m, __shfl_xor_sync(0xffffffffu, m, o));
    __shared__ float sm[4], ss[4];
    int w = t >> 5, lane = t & 31;
    if (lane == 0) sm[w] = m;
    __syncthreads();
    m = fmaxf(fmaxf(sm[0], sm[1]), fmaxf(sm[2], sm[3]));
    float s = __expf(v.x - m) + __expf(v.y - m) + __expf(v.z - m) + __expf(v.w - m);
#pragma unroll
    for (int o = 16; o > 0; o >>= 1) s += __shfl_xor_sync(0xffffffffu, s, o);
    if (lane == 0) ss[w] = s;
    __syncthreads();
    if (t == 0) {
        g_rm[row] = m;
        g_ri[row] = 1.0f / (ss[0] + ss[1] + ss[2] + ss[3]);
    }
}

// ============================================================================
// Kernel 7: out = softmax(scores) @ V (via V^T), softmax fused into A fill.
// grid(x=2 over e, y=4 over p, z=bc), 128 thr
// ============================================================================
__global__ void __launch_bounds__(128) k_av_m(float* __restrict__ out)
{
    extern __shared__ char dyn[];
    float* s_m   = reinterpret_cast<float*>(dyn + NSTAGE * STAGE_BYTES);
    float* s_inv = s_m + 128;
    int bc = blockIdx.z;
    int m0 = blockIdx.y * BM;          // p
    int n0 = blockIdx.x * BN;          // e
    int t = threadIdx.x, lane = t & 31, wid = t >> 5;

    size_t rowbase = (size_t)bc * P + m0;
    s_m[t]   = g_rm[rowbase + t];
    s_inv[t] = g_ri[rowbase + t];
    __syncthreads();   // s_m/s_inv are read cross-thread by the prologue fills

    const float* At = g_At + (size_t)bc * P * P + (size_t)m0 * P;
    size_t vbase = (size_t)bc * D * P;

    float acc[4][8][4] = {};
    gemm_tiles3_av(dyn, At, g_VTh + vbase, g_VTl + vbase, P, n0,
                   P / BKF, acc, t, lane, wid, s_m, s_inv);

    int wm = (wid & 1) * 64, wn = (wid >> 1) * 64;
    int gr = lane >> 2, gc = (lane & 3) * 2;
    float* Ob = out + (size_t)bc * P * D;
#pragma unroll
    for (int mt = 0; mt < 4; ++mt)
#pragma unroll
        for (int nt = 0; nt < 8; ++nt) {
            int p0 = m0 + wm + mt * 16 + gr;
            int e0 = n0 + wn + nt * 8 + gc;
            *reinterpret_cast<float2*>(&Ob[(size_t)p0 * D + e0]) =
                make_float2(acc[mt][nt][0], acc[mt][nt][1]);
            *reinterpret_cast<float2*>(&Ob[(size_t)(p0 + 8) * D + e0]) =
                make_float2(acc[mt][nt][2], acc[mt][nt][3]);
        }
}

// ============================================================================
extern "C" void kernel_launch(void* const* d_in, const int* /*in_sizes*/, int /*n_in*/,
                              void* d_out, int /*out_size*/)
{
    const float* query = (const float*)d_in[0];
    const float* aw    = (const float*)d_in[1];
    const float* Wq    = (const float*)d_in[2];
    const float* Wk    = (const float*)d_in[3];
    const float* Wv    = (const float*)d_in[4];
    const float* bq    = (const float*)d_in[5];
    const float* bk    = (const float*)d_in[6];
    const float* bv    = (const float*)d_in[7];
    float* out = (float*)d_out;

    cudaFuncSetAttribute(k_projQK,  cudaFuncAttributeMaxDynamicSharedMemorySize, DYN_BYTES);
    cudaFuncSetAttribute(k_projVT,  cudaFuncAttributeMaxDynamicSharedMemorySize, DYN_BYTES);
    cudaFuncSetAttribute(k_scores_m,cudaFuncAttributeMaxDynamicSharedMemorySize, DYN_BYTES);
    cudaFuncSetAttribute(k_av_m,    cudaFuncAttributeMaxDynamicSharedMemorySize, DYN_BYTES);

    k_prep<<<(B * P * D / 4) / 256, 256>>>(query, aw);
    k_prep_wt<<<(3 * C * D * D / 4) / 256, 256>>>(Wq, Wk, Wv);
    k_projQK<<<dim3(D / BN, P / BM, B * C * 2), 128, DYN_BYTES>>>(bq, bk);
    k_projVT<<<dim3(P / BN, D / BM, B * C), 128, DYN_BYTES>>>(bv);
    k_scores_m<<<dim3(P / BN, P / BM, B * C), 128, DYN_BYTES>>>();
    k_stats<<<B * C * P, 128>>>();
    k_av_m<<<dim3(D / BN, P / BM, B * C), 128, DYN_BYTES>>>(out);
}